// round 4
// baseline (speedup 1.0000x reference)
#include <cuda_runtime.h>
#include <cuda_bf16.h>
#include <cstdint>

#define NN 100000
#define EE 1600000
#define HH 128
#define LL 4
#define GG 256
#define CC 10

// ---------------- scratch (static device globals; no allocation) ----------------
__device__ float          g_hA[NN * HH];   // fp32 stage-4 output for head
__device__ float          g_hT[NN * HH];   // SpMM output (GEMM A input)
__device__ __nv_bfloat162 g_hB[NN * HH / 2]; // bf16 feature copy for gathers
__device__ int   g_deg[NN];
__device__ float g_dinv[NN];
__device__ int   g_offs[NN + 1];
__device__ int   g_cursor[NN];
__device__ int   g_col[EE];
__device__ float g_w[EE];
__device__ int   g_part[512];
__device__ int   g_starts[GG + 1];
__device__ float g_scale[(LL + 1) * HH];
__device__ float g_bias[(LL + 1) * HH];

// ---------------- graph preprocessing ----------------
__global__ void k_zero_deg() {
    int i = blockIdx.x * blockDim.x + threadIdx.x;
    if (i < NN) g_deg[i] = 0;
}
__global__ void k_count(const int* __restrict__ dst) {
    int e = blockIdx.x * blockDim.x + threadIdx.x;
    if (e < EE) atomicAdd(&g_deg[dst[e]], 1);
}
__global__ void k_scan1() {   // per-block exclusive scan of degrees + dinv
    __shared__ int s[256];
    int t = threadIdx.x;
    int i = blockIdx.x * 256 + t;
    int v = (i < NN) ? g_deg[i] : 0;
    if (i < NN) g_dinv[i] = rsqrtf((float)v + 1.0f);
    s[t] = v;
    __syncthreads();
    #pragma unroll
    for (int off = 1; off < 256; off <<= 1) {
        int x = (t >= off) ? s[t - off] : 0;
        __syncthreads();
        s[t] += x;
        __syncthreads();
    }
    if (i < NN) g_offs[i] = s[t] - v;
    if (t == 255) g_part[blockIdx.x] = s[255];
}
__global__ void k_scan2() {
    __shared__ int s[512];
    int t = threadIdx.x;
    int v = (t < 391) ? g_part[t] : 0;
    s[t] = v;
    __syncthreads();
    #pragma unroll
    for (int off = 1; off < 512; off <<= 1) {
        int x = (t >= off) ? s[t - off] : 0;
        __syncthreads();
        s[t] += x;
        __syncthreads();
    }
    if (t < 391) g_part[t] = s[t] - v;
}
__global__ void k_scan3() {
    int i = blockIdx.x * blockDim.x + threadIdx.x;
    if (i < NN) {
        int o = g_offs[i] + g_part[i >> 8];
        g_offs[i] = o;
        g_cursor[i] = o;
    }
    if (i == 0) g_offs[NN] = EE;
}
__global__ void k_fill(const int* __restrict__ src, const int* __restrict__ dst) {
    int e = blockIdx.x * blockDim.x + threadIdx.x;
    if (e < EE) {
        int s = src[e], d = dst[e];
        int p = atomicAdd(&g_cursor[d], 1);
        g_col[p] = s;
        g_w[p] = g_dinv[s] * g_dinv[d];
    }
}
__global__ void k_prep(const float* __restrict__ b_in, const float* __restrict__ gam,
                       const float* __restrict__ bet, const float* __restrict__ rm,
                       const float* __restrict__ rv, const float* __restrict__ bs) {
    int t = threadIdx.x;
    if (t < HH) {
        g_scale[t] = 1.0f;
        g_bias[t]  = b_in[t];
        for (int l = 0; l < LL; l++) {
            float s = gam[l * HH + t] * rsqrtf(rv[l * HH + t] + 1e-5f);
            g_scale[(l + 1) * HH + t] = s;
            g_bias[(l + 1) * HH + t]  = (bs[l * HH + t] - rm[l * HH + t]) * s + bet[l * HH + t];
        }
    }
}
__global__ void k_starts(const int* __restrict__ batch) {
    int t = threadIdx.x;
    if (t <= GG) {
        int lo = 0, hi = NN;
        while (lo < hi) {
            int m = (lo + hi) >> 1;
            if (batch[m] < t) lo = m + 1; else hi = m;
        }
        g_starts[t] = lo;
    }
}

// ---------------- SpMM (bf16 gather): out = (A_norm + diag(dinv^2)) @ h_bf ----------------
__device__ __forceinline__ float4 bf4_to_f4(uint2 u) {
    __nv_bfloat162 p0 = *reinterpret_cast<__nv_bfloat162*>(&u.x);
    __nv_bfloat162 p1 = *reinterpret_cast<__nv_bfloat162*>(&u.y);
    float2 a = __bfloat1622float2(p0);
    float2 b = __bfloat1622float2(p1);
    return make_float4(a.x, a.y, b.x, b.y);
}
__global__ void k_spmm(const uint2* __restrict__ hb, float4* __restrict__ hout) {
    int warp = (blockIdx.x * blockDim.x + threadIdx.x) >> 5;
    int lane = threadIdx.x & 31;
    if (warp >= NN) return;
    float di = g_dinv[warp];
    float sw = di * di;
    float4 self = bf4_to_f4(hb[warp * 32 + lane]);
    float4 acc = make_float4(self.x * sw, self.y * sw, self.z * sw, self.w * sw);
    int s = g_offs[warp], e = g_offs[warp + 1];
    int j = s;
    for (; j + 3 < e; j += 4) {
        float w0 = g_w[j];     int c0 = g_col[j];
        float w1 = g_w[j + 1]; int c1 = g_col[j + 1];
        float w2 = g_w[j + 2]; int c2 = g_col[j + 2];
        float w3 = g_w[j + 3]; int c3 = g_col[j + 3];
        float4 v0 = bf4_to_f4(hb[c0 * 32 + lane]);
        float4 v1 = bf4_to_f4(hb[c1 * 32 + lane]);
        float4 v2 = bf4_to_f4(hb[c2 * 32 + lane]);
        float4 v3 = bf4_to_f4(hb[c3 * 32 + lane]);
        acc.x += w0 * v0.x; acc.y += w0 * v0.y; acc.z += w0 * v0.z; acc.w += w0 * v0.w;
        acc.x += w1 * v1.x; acc.y += w1 * v1.y; acc.z += w1 * v1.z; acc.w += w1 * v1.w;
        acc.x += w2 * v2.x; acc.y += w2 * v2.y; acc.z += w2 * v2.z; acc.w += w2 * v2.w;
        acc.x += w3 * v3.x; acc.y += w3 * v3.y; acc.z += w3 * v3.z; acc.w += w3 * v3.w;
    }
    for (; j < e; j++) {
        float w0 = g_w[j]; int c0 = g_col[j];
        float4 v0 = bf4_to_f4(hb[c0 * 32 + lane]);
        acc.x += w0 * v0.x; acc.y += w0 * v0.y; acc.z += w0 * v0.z; acc.w += w0 * v0.w;
    }
    hout[warp * 32 + lane] = acc;
}

// ---------------- GEMM (TF32 tensor core): C = relu((A @ B) * scale + bias) ----------------
#define APAD 4
#define BPAD 8
#define AS_W (HH + APAD)            // 132
#define BS_W (HH + BPAD)            // 136
#define GEMM_SMEM ((64 * AS_W + 128 * BS_W) * 4)

__device__ __forceinline__ void mma_tf32(float& c0, float& c1, float& c2, float& c3,
                                         uint32_t a0, uint32_t a1, uint32_t a2, uint32_t a3,
                                         uint32_t b0, uint32_t b1) {
    asm volatile(
        "mma.sync.aligned.m16n8k8.row.col.f32.tf32.tf32.f32 "
        "{%0,%1,%2,%3}, {%4,%5,%6,%7}, {%8,%9}, {%0,%1,%2,%3};\n"
        : "+f"(c0), "+f"(c1), "+f"(c2), "+f"(c3)
        : "r"(a0), "r"(a1), "r"(a2), "r"(a3), "r"(b0), "r"(b1));
}

__global__ __launch_bounds__(256, 2)
void k_gemm(const float* __restrict__ A, const float* __restrict__ B,
            float* __restrict__ Cfp, __nv_bfloat162* __restrict__ Cbf,
            int M, int stage) {
    extern __shared__ float sm[];
    float (*As)[AS_W] = (float (*)[AS_W])sm;
    float (*Bs)[BS_W] = (float (*)[BS_W])(sm + 64 * AS_W);
    int tid = threadIdx.x;
    int rb = blockIdx.x * 64;

    const float4* B4 = (const float4*)B;
    #pragma unroll
    for (int i = tid; i < 4096; i += 256) {
        int r = i >> 5, c = i & 31;
        *(float4*)&Bs[r][c * 4] = B4[i];
    }
    #pragma unroll
    for (int i = tid; i < 2048; i += 256) {
        int r = i >> 5, c = i & 31;
        float4 v = make_float4(0.f, 0.f, 0.f, 0.f);
        if (rb + r < M) v = ((const float4*)A)[(size_t)(rb + r) * 32 + c];
        *(float4*)&As[r][c * 4] = v;
    }
    __syncthreads();

    int w = tid >> 5;
    int lane = tid & 31;
    int g = lane >> 2, tg = lane & 3;
    int warp_m = (w >> 2) * 32;
    int warp_n = (w & 3) * 32;

    float acc[2][4][4];
    #pragma unroll
    for (int mt = 0; mt < 2; mt++)
        #pragma unroll
        for (int nt = 0; nt < 4; nt++)
            #pragma unroll
            for (int q = 0; q < 4; q++) acc[mt][nt][q] = 0.f;

    #pragma unroll 4
    for (int kk = 0; kk < 16; kk++) {
        int k0 = kk * 8;
        uint32_t a[2][4], b[4][2];
        #pragma unroll
        for (int mt = 0; mt < 2; mt++) {
            int r = warp_m + 16 * mt + g;
            a[mt][0] = __float_as_uint(As[r][k0 + tg]);
            a[mt][1] = __float_as_uint(As[r + 8][k0 + tg]);
            a[mt][2] = __float_as_uint(As[r][k0 + tg + 4]);
            a[mt][3] = __float_as_uint(As[r + 8][k0 + tg + 4]);
        }
        #pragma unroll
        for (int nt = 0; nt < 4; nt++) {
            int cc = warp_n + 8 * nt + g;
            b[nt][0] = __float_as_uint(Bs[k0 + tg][cc]);
            b[nt][1] = __float_as_uint(Bs[k0 + tg + 4][cc]);
        }
        #pragma unroll
        for (int mt = 0; mt < 2; mt++)
            #pragma unroll
            for (int nt = 0; nt < 4; nt++)
                mma_tf32(acc[mt][nt][0], acc[mt][nt][1], acc[mt][nt][2], acc[mt][nt][3],
                         a[mt][0], a[mt][1], a[mt][2], a[mt][3], b[nt][0], b[nt][1]);
    }

    const float* sc = g_scale + stage * HH;
    const float* bi = g_bias + stage * HH;
    #pragma unroll
    for (int mt = 0; mt < 2; mt++) {
        int r0 = rb + warp_m + 16 * mt + g;
        #pragma unroll
        for (int nt = 0; nt < 4; nt++) {
            int c0 = warp_n + 8 * nt + 2 * tg;
            float s0 = sc[c0], s1 = sc[c0 + 1];
            float q0 = bi[c0], q1 = bi[c0 + 1];
            #pragma unroll
            for (int h = 0; h < 2; h++) {
                int row = r0 + 8 * h;
                if (row < M) {
                    float ox = fmaxf(acc[mt][nt][2 * h]     * s0 + q0, 0.0f);
                    float oy = fmaxf(acc[mt][nt][2 * h + 1] * s1 + q1, 0.0f);
                    if (Cfp) *(float2*)&Cfp[(size_t)row * 128 + c0] = make_float2(ox, oy);
                    if (Cbf) Cbf[(size_t)row * 64 + (c0 >> 1)] = __floats2bfloat162_rn(ox, oy);
                }
            }
        }
    }
}

// ---------------- pool + MLP head (256 threads, 2-way row split) ----------------
__global__ void k_head(const float* __restrict__ h,
                       const float* __restrict__ fc1w, const float* __restrict__ fc1b,
                       const float* __restrict__ fc2w, const float* __restrict__ fc2b,
                       float* __restrict__ out) {
    __shared__ float ge[128];
    __shared__ float red[128];
    __shared__ float hid[64];
    int g = blockIdx.x, t = threadIdx.x;
    int ch = t & 127, half = t >> 7;
    int s = g_starts[g], e = g_starts[g + 1];
    float sum = 0.f;
    for (int r = s + half; r < e; r += 2) sum += h[(size_t)r * 128 + ch];
    if (half) red[ch] = sum;
    __syncthreads();
    if (!half) {
        float tot = sum + red[ch];
        ge[ch] = tot / fmaxf((float)(e - s), 1.0f);
    }
    __syncthreads();
    if (t < 64) {
        float a = fc1b[t];
        #pragma unroll 8
        for (int k = 0; k < 128; k++) a += ge[k] * fc1w[k * 64 + t];
        hid[t] = fmaxf(a, 0.0f);
    }
    __syncthreads();
    if (t < 10) {
        float a = fc2b[t];
        #pragma unroll 8
        for (int k = 0; k < 64; k++) a += hid[k] * fc2w[k * 10 + t];
        out[g * 10 + t] = a;
    }
}

// ---------------- launch ----------------
extern "C" void kernel_launch(void* const* d_in, const int* in_sizes, int n_in,
                              void* d_out, int out_size) {
    const float* x      = (const float*)d_in[0];
    const int*   ei     = (const int*)d_in[1];
    const int*   src    = ei;
    const int*   dst    = ei + EE;
    const int*   batch  = (const int*)d_in[2];
    const float* W_in   = (const float*)d_in[3];
    const float* b_in   = (const float*)d_in[4];
    const float* Ws     = (const float*)d_in[5];
    const float* bs     = (const float*)d_in[6];
    const float* gammas = (const float*)d_in[7];
    const float* betas  = (const float*)d_in[8];
    const float* rmeans = (const float*)d_in[9];
    const float* rvars  = (const float*)d_in[10];
    const float* fc1_w  = (const float*)d_in[11];
    const float* fc1_b  = (const float*)d_in[12];
    const float* fc2_w  = (const float*)d_in[13];
    const float* fc2_b  = (const float*)d_in[14];
    float* out = (float*)d_out;

    cudaFuncSetAttribute(k_gemm, cudaFuncAttributeMaxDynamicSharedMemorySize, GEMM_SMEM);

    float *hA, *hT;
    __nv_bfloat162* hB;
    cudaGetSymbolAddress((void**)&hA, g_hA);
    cudaGetSymbolAddress((void**)&hT, g_hT);
    cudaGetSymbolAddress((void**)&hB, g_hB);

    const int NB = (NN + 255) / 256;      // 391
    const int EB = (EE + 255) / 256;      // 6250

    // CSR build
    k_zero_deg<<<NB, 256>>>();
    k_count<<<EB, 256>>>(dst);
    k_scan1<<<NB, 256>>>();
    k_scan2<<<1, 512>>>();
    k_scan3<<<NB, 256>>>();
    k_fill<<<EB, 256>>>(src, dst);
    k_prep<<<1, 128>>>(b_in, gammas, betas, rmeans, rvars, bs);
    k_starts<<<1, 257>>>(batch);

    const int GB = (NN + 63) / 64;        // 1563 gemm blocks
    const int SB = (NN * 32 + 255) / 256; // 12500 spmm blocks

    // input projection -> bf16 features only
    k_gemm<<<GB, 256, GEMM_SMEM>>>(x, W_in, nullptr, hB, NN, 0);

    // 4 GCN layers
    for (int l = 0; l < LL; l++) {
        k_spmm<<<SB, 256>>>((const uint2*)hB, (float4*)hT);
        bool last = (l == LL - 1);
        k_gemm<<<GB, 256, GEMM_SMEM>>>(hT, Ws + (size_t)l * HH * HH,
                                       last ? hA : nullptr, last ? nullptr : hB,
                                       NN, l + 1);
    }

    // pool + head
    k_head<<<GG, 128 * 2>>>(hA, fc1_w, fc1_b, fc2_w, fc2_b, out);
}